// round 8
// baseline (speedup 1.0000x reference)
#include <cuda_runtime.h>

#define DD 8
#define BX 32            // m-pairs per block (tx) -> 64 m columns
#define BY 8             // ty; each thread does rows ty and ty+8 (two sequential phases)

typedef unsigned long long u64;

// constant layout: [0..63] w | [64..191] ks (per j: 8x KMm, 8x -Km) | [192..223] pl (per j: lj2,alpha,beta,gamma) | [224] sig0
#define C_W   0
#define C_KS  64
#define C_PL  192
#define C_S0  224
#define C_TOT 232

__constant__ __align__(16) u64 cC[C_TOT];
__device__   __align__(16) u64 gScratch[C_TOT];

// packed f32x2 ops (Blackwell sm_103a)
#define FMA2(d,a,b,c) asm("fma.rn.f32x2 %0, %1, %2, %3;" : "=l"(d) : "l"(a), "l"(b), "l"(c))
#define MUL2(d,a,b)   asm("mul.rn.f32x2 %0, %1, %2;"     : "=l"(d) : "l"(a), "l"(b))
#define ADD2(d,a,b)   asm("add.rn.f32x2 %0, %1, %2;"     : "=l"(d) : "l"(a), "l"(b))

__device__ __forceinline__ u64 pack2(float lo, float hi) {
    u64 r; asm("mov.b64 %0, {%1, %2};" : "=l"(r) : "f"(lo), "f"(hi)); return r;
}
__device__ __forceinline__ void unpack2(u64 v, float& lo, float& hi) {
    asm("mov.b64 {%0, %1}, %2;" : "=f"(lo), "=f"(hi) : "l"(v));
}
__device__ __forceinline__ float ex2a(float x) {
    float r; asm("ex2.approx.f32 %0, %1;" : "=f"(r) : "f"(x)); return r;
}
__device__ __forceinline__ u64 dup(float v) {
    unsigned u = __float_as_uint(v);
    return ((u64)u << 32) | (u64)u;
}

// ---------- setup kernel: derive constants once ----------
__global__ void setup_kernel(const float* __restrict__ L, const float* __restrict__ sig)
{
    int tid = threadIdx.x;            // 0..63
    int c = tid >> 3, j = tid & 7;
    float Ljc = L[j * DD + c];
    float inv2_jc = 1.0f / (Ljc * Ljc);
    float L0c = L[c];
    float inv2_0c = 1.0f / (L0c * L0c);
    float Mcj = inv2_0c + inv2_jc;
    float L0j = L[j];
    float lj2 = L0j * L0j;
    float Kcj = sig[j] / (lj2 * lj2) * Mcj * Mcj;
    gScratch[C_KS + j * 16 + c]     = dup(Kcj / Mcj);
    gScratch[C_KS + j * 16 + 8 + c] = dup(-Kcj);
    float Lak = L[c * DD + j];
    gScratch[C_W + c * DD + j] = dup(-0.5f * 1.44269504088896340736f / (Lak * Lak));
    if (c == j) {
        int l = c;
        float tl = Mcj;                       // M[l][l]
        float c1 = 5.0f * tl + lj2 * tl * tl;
        float c2 = tl * tl;
        float c3 = 2.0f + lj2 * tl;
        float F  = sig[l] / (lj2 * lj2);
        float Kd = Kcj;
        float Md = 1.0f / tl;
        gScratch[C_PL + l * 4 + 0] = dup(lj2);
        gScratch[C_PL + l * 4 + 1] = dup(F * c3 - Kd * Md * lj2);    // alpha
        gScratch[C_PL + l * 4 + 2] = dup(-F * c1 + Kd * (Md + lj2)); // beta
        gScratch[C_PL + l * 4 + 3] = dup(F * c2 - Kd);               // gamma
    }
    if (tid == 0) gScratch[C_S0] = dup(sig[0]);
}

// ---------- main kernel ----------
// out[n,m] = sigma0 * E0 * S_total
//   d_k = (x1[n,k]-x2[m,k])^2 ; E_a = exp2( sum_k d_k * w[a,k] )
//   S_total = sum_j E_j * [ acc_j*(lj2_j - d_j) + (alpha + beta d + gamma d^2)_j * E_j ]
//   acc_j = sum_c (KMm[c,j] - Km[c,j] d_c) E_c

__global__ __launch_bounds__(256, 4) void taylor_rbf_kernel(
    const float* __restrict__ x1, const float* __restrict__ x2,
    float* __restrict__ out, int N, int M)
{
    __shared__ __align__(16) u64 x1d[16 * DD];   // dup(x1[n0+r][k]), r=0..15
    __shared__ __align__(16) u64 nx2[DD * BX];   // (-x2[m0+2p][k], -x2[m0+2p+1][k])

    const int tx = threadIdx.x;          // 0..31
    const int ty = threadIdx.y;          // 0..7
    const int tid = ty * BX + tx;

    // ---- stage x tiles ----
    const int n0 = blockIdx.y * 16, m0 = blockIdx.x * (2 * BX);
    {   // nx2: 256 entries, one per thread
        int k = tid >> 5, p = tid & 31;
        int mm = m0 + 2 * p;
        float a = (mm     < M) ? x2[mm * DD + k]       : 0.0f;
        float b = (mm + 1 < M) ? x2[(mm + 1) * DD + k] : 0.0f;
        nx2[k * BX + p] = pack2(-a, -b);
    }
    if (tid < 128) {  // x1d: 128 entries
        int r = tid >> 3, k = tid & 7;
        int nn = n0 + r;
        x1d[r * DD + k] = dup((nn < N) ? x1[nn * DD + k] : 0.0f);
    }
    __syncthreads();

    const int m = m0 + 2 * tx;
    if (m >= M) return;

    const u64 negone = dup(-1.0f);
    const bool full = (m + 1 < M);

    // ---- two sequential phases: rows ty and ty+8 ----
#pragma unroll
    for (int ph = 0; ph < 2; ph++) {
        const int row = ty + 8 * ph;
        const int n = n0 + row;
        if (n >= N) continue;

        // d_k
        u64 d[DD];
#pragma unroll
        for (int k = 0; k < DD; k++) {
            u64 f; ADD2(f, x1d[row * DD + k], nx2[k * BX + tx]);
            MUL2(d[k], f, f);
        }

        // E_a = exp2( d . w_a )
        u64 E[DD];
#pragma unroll
        for (int a = 0; a < DD; a++) {
            const u64* wr = &cC[C_W + a * DD];
            u64 s;
            MUL2(s, d[0], wr[0]);
            FMA2(s, d[1], wr[1], s);
            FMA2(s, d[2], wr[2], s);
            FMA2(s, d[3], wr[3], s);
            FMA2(s, d[4], wr[4], s);
            FMA2(s, d[5], wr[5], s);
            FMA2(s, d[6], wr[6], s);
            FMA2(s, d[7], wr[7], s);
            float lo, hi;
            unpack2(s, lo, hi);
            E[a] = pack2(ex2a(lo), ex2a(hi));
        }

        // merged S + corr loop over j
        u64 S = dup(0.0f);
#pragma unroll
        for (int j = 0; j < DD; j++) {
            const u64* kmm = &cC[C_KS + j * 16];       // 8x KMm
            const u64* nkm = &cC[C_KS + j * 16 + 8];   // 8x -Km
            const u64* pl  = &cC[C_PL + j * 4];        // lj2, alpha, beta, gamma

            u64 acc, wp;
            // acc = sum_c (KMm_c - Km_c * d_c) * E_c   (two partial chains for ILP)
            u64 acc2;
            FMA2(wp, nkm[0], d[0], kmm[0]);  MUL2(acc,  wp, E[0]);
            FMA2(wp, nkm[1], d[1], kmm[1]);  MUL2(acc2, wp, E[1]);
            FMA2(wp, nkm[2], d[2], kmm[2]);  FMA2(acc,  wp, E[2], acc);
            FMA2(wp, nkm[3], d[3], kmm[3]);  FMA2(acc2, wp, E[3], acc2);
            FMA2(wp, nkm[4], d[4], kmm[4]);  FMA2(acc,  wp, E[4], acc);
            FMA2(wp, nkm[5], d[5], kmm[5]);  FMA2(acc2, wp, E[5], acc2);
            FMA2(wp, nkm[6], d[6], kmm[6]);  FMA2(acc,  wp, E[6], acc);
            FMA2(wp, nkm[7], d[7], kmm[7]);  FMA2(acc2, wp, E[7], acc2);
            ADD2(acc, acc, acc2);

            // S += E_j * ( acc*(lj2-d_j) + poly_j * E_j )
            u64 t;  FMA2(t, d[j], negone, pl[0]);      // lj2 - d
            u64 u_; FMA2(u_, pl[3], d[j], pl[2]);      // gamma*d + beta
            u64 py; FMA2(py, d[j], u_, pl[1]);         // d*(.) + alpha
            u64 v;  MUL2(v, acc, t);
            FMA2(v, py, E[j], v);
            FMA2(S, E[j], v, S);
        }

        // out = sig0 * E0 * S
        u64 e0; MUL2(e0, E[0], cC[C_S0]);
        u64 r;  MUL2(r, S, e0);

        long idx = (long)n * M + m;
        if (full) *reinterpret_cast<u64*>(&out[idx]) = r;
        else { float lo, hi; unpack2(r, lo, hi); out[idx] = lo; }
    }
}

extern "C" void kernel_launch(void* const* d_in, const int* in_sizes, int n_in,
                              void* d_out, int out_size)
{
    const float* x1  = (const float*)d_in[0];
    const float* x2  = (const float*)d_in[1];
    const float* L   = (const float*)d_in[2];
    const float* sig = (const float*)d_in[3];
    float* out = (float*)d_out;

    int N = in_sizes[0] / DD;
    int M = in_sizes[1] / DD;

    setup_kernel<<<1, 64>>>(L, sig);

    void* scratch_addr = nullptr;
    cudaGetSymbolAddress(&scratch_addr, gScratch);
    cudaMemcpyToSymbolAsync(cC, scratch_addr, C_TOT * sizeof(u64), 0,
                            cudaMemcpyDeviceToDevice, 0);

    dim3 block(BX, BY);                                    // 256 threads
    dim3 grid((M + 2 * BX - 1) / (2 * BX), (N + 15) / 16);
    taylor_rbf_kernel<<<grid, block>>>(x1, x2, out, N, M);
}

// round 9
// speedup vs baseline: 1.0763x; 1.0763x over previous
#include <cuda_runtime.h>

#define DD 8

typedef unsigned long long u64;

// packed f32x2 ops (Blackwell sm_103a)
#define FMA2(d,a,b,c) asm("fma.rn.f32x2 %0, %1, %2, %3;" : "=l"(d) : "l"(a), "l"(b), "l"(c))
#define MUL2(d,a,b)   asm("mul.rn.f32x2 %0, %1, %2;"     : "=l"(d) : "l"(a), "l"(b))
#define ADD2(d,a,b)   asm("add.rn.f32x2 %0, %1, %2;"     : "=l"(d) : "l"(a), "l"(b))

__device__ __forceinline__ u64 pack2(float lo, float hi) {
    u64 r; asm("mov.b64 %0, {%1, %2};" : "=l"(r) : "f"(lo), "f"(hi)); return r;
}
__device__ __forceinline__ void unpack2(u64 v, float& lo, float& hi) {
    asm("mov.b64 {%0, %1}, %2;" : "=f"(lo), "=f"(hi) : "l"(v));
}
__device__ __forceinline__ float ex2a(float x) {
    float r; asm("ex2.approx.f32 %0, %1;" : "=f"(r) : "f"(x)); return r;
}
__device__ __forceinline__ u64 dup(float v) {
    unsigned u = __float_as_uint(v);
    return ((u64)u << 32) | (u64)u;
}

// out[n,m] = sigma0 * E0 * S_total
//   d_k = (x1[n,k]-x2[m,k])^2 ; E_a = exp2( sum_k d_k * w[a,k] ), w = -0.5*log2e/L^2
//   S_total = sum_j E_j * [ acc_j*(lj2_j - d_j) + (alpha_j + beta_j d_j + gamma_j d_j^2) * E_j ]
//   acc_j = sum_c (KMm[c,j] - Km[c,j] d_c) E_c
//
// Block tile: 8 n-rows x 128 m-cols. 128 threads (32x4).
// Each thread: 2 rows (ty, ty+4) x 2 m-pairs (tx, tx+32) = 4 packed pairs = 8 outputs.

__global__ __launch_bounds__(128, 3) void taylor_rbf_kernel(
    const float* __restrict__ x1, const float* __restrict__ x2,
    const float* __restrict__ L, const float* __restrict__ sig,
    float* __restrict__ out, int N, int M)
{
    __shared__ __align__(16) u64 wD[DD * DD];    // dup(w[a][k])
    __shared__ __align__(16) u64 ksD[DD * 16];   // per j: 8x dup(KMm[c][j]), 8x dup(-Km[c][j])
    __shared__ __align__(16) u64 plD[DD * 4];    // per j: (lj2, alpha, beta, gamma)
    __shared__ __align__(16) u64 x1d[8 * DD];    // dup(x1[n0+r][k]), r=0..7
    __shared__ __align__(16) u64 nx2[DD * 64];   // (-x2[m0+2p][k], -x2[m0+2p+1][k]), p=0..63
    __shared__ u64 sig0d;

    const int tx = threadIdx.x;          // 0..31
    const int ty = threadIdx.y;          // 0..3
    const int tid = ty * 32 + tx;        // 0..127

    // ---- per-block constant derivation (64 threads) ----
    if (tid < 64) {
        int c = tid >> 3, j = tid & 7;
        float Ljc = L[j * DD + c];
        float inv2_jc = 1.0f / (Ljc * Ljc);
        float L0c = L[c];
        float inv2_0c = 1.0f / (L0c * L0c);
        float Mcj = inv2_0c + inv2_jc;
        float L0j = L[j];
        float lj2 = L0j * L0j;
        float Kcj = sig[j] / (lj2 * lj2) * Mcj * Mcj;
        ksD[j * 16 + c]     = dup(Kcj / Mcj);
        ksD[j * 16 + 8 + c] = dup(-Kcj);
        float Lak = L[c * DD + j];
        wD[c * DD + j] = dup(-0.5f * 1.44269504088896340736f / (Lak * Lak));
        if (c == j) {
            int l = c;
            float tl = Mcj;                       // M[l][l]
            float c1 = 5.0f * tl + lj2 * tl * tl;
            float c2 = tl * tl;
            float c3 = 2.0f + lj2 * tl;
            float F  = sig[l] / (lj2 * lj2);
            float Kd = Kcj;
            float Md = 1.0f / tl;
            plD[l * 4 + 0] = dup(lj2);
            plD[l * 4 + 1] = dup(F * c3 - Kd * Md * lj2);    // alpha
            plD[l * 4 + 2] = dup(-F * c1 + Kd * (Md + lj2)); // beta
            plD[l * 4 + 3] = dup(F * c2 - Kd);               // gamma
        }
        if (tid == 0) sig0d = dup(sig[0]);
    }

    // ---- stage x tiles ----
    const int n0 = blockIdx.y * 8, m0 = blockIdx.x * 128;
#pragma unroll
    for (int i = 0; i < 4; i++) {        // nx2: 512 entries, 4 per thread
        int idx = tid + 128 * i;
        int k = idx >> 6, p = idx & 63;
        int mm = m0 + 2 * p;
        float a = (mm     < M) ? x2[mm * DD + k]       : 0.0f;
        float b = (mm + 1 < M) ? x2[(mm + 1) * DD + k] : 0.0f;
        nx2[k * 64 + p] = pack2(-a, -b);
    }
    if (tid < 64) {                      // x1d: 64 entries
        int r = tid >> 3, k = tid & 7;
        int nn = n0 + r;
        x1d[r * DD + k] = dup((nn < N) ? x1[nn * DD + k] : 0.0f);
    }
    __syncthreads();

    const u64 negone = dup(-1.0f);

    // ---- d for 4 pairs: rows {ty, ty+4}, pair-cols {tx, tx+32} ----
    u64 d[2][2][DD], E[2][2][DD];
#pragma unroll
    for (int k = 0; k < DD; k++) {
        u64 xv0 = nx2[k * 64 + tx];
        u64 xv1 = nx2[k * 64 + tx + 32];
#pragma unroll
        for (int r = 0; r < 2; r++) {
            u64 xr = x1d[(ty + 4 * r) * DD + k];
            u64 f0; ADD2(f0, xr, xv0);  MUL2(d[r][0][k], f0, f0);
            u64 f1; ADD2(f1, xr, xv1);  MUL2(d[r][1][k], f1, f1);
        }
    }

    // ---- E_a = exp2( d . w_a ) for 4 pairs ----
#pragma unroll
    for (int a = 0; a < DD; a++) {
        const u64* wr = &wD[a * DD];
        u64 w0 = wr[0], w1 = wr[1], w2 = wr[2], w3 = wr[3];
        u64 w4 = wr[4], w5 = wr[5], w6 = wr[6], w7 = wr[7];
#pragma unroll
        for (int r = 0; r < 2; r++)
#pragma unroll
        for (int q = 0; q < 2; q++) {
            u64 s;
            MUL2(s, d[r][q][0], w0);
            FMA2(s, d[r][q][1], w1, s);
            FMA2(s, d[r][q][2], w2, s);
            FMA2(s, d[r][q][3], w3, s);
            FMA2(s, d[r][q][4], w4, s);
            FMA2(s, d[r][q][5], w5, s);
            FMA2(s, d[r][q][6], w6, s);
            FMA2(s, d[r][q][7], w7, s);
            float lo, hi;
            unpack2(s, lo, hi);
            E[r][q][a] = pack2(ex2a(lo), ex2a(hi));
        }
    }

    // ---- merged S + corr loop over j, 4 pairs share constants ----
    u64 S[2][2];
    S[0][0] = S[0][1] = S[1][0] = S[1][1] = dup(0.0f);
#pragma unroll
    for (int j = 0; j < DD; j++) {
        const u64* kmm = &ksD[j * 16];       // 8x KMm
        const u64* nkm = &ksD[j * 16 + 8];   // 8x -Km
        const u64* pl  = &plD[j * 4];        // lj2, alpha, beta, gamma
        u64 lj2 = pl[0], al = pl[1], be = pl[2], ga = pl[3];
#pragma unroll
        for (int r = 0; r < 2; r++)
#pragma unroll
        for (int q = 0; q < 2; q++) {
            u64 acc, acc2, wp;
            FMA2(wp, nkm[0], d[r][q][0], kmm[0]);  MUL2(acc,  wp, E[r][q][0]);
            FMA2(wp, nkm[1], d[r][q][1], kmm[1]);  MUL2(acc2, wp, E[r][q][1]);
            FMA2(wp, nkm[2], d[r][q][2], kmm[2]);  FMA2(acc,  wp, E[r][q][2], acc);
            FMA2(wp, nkm[3], d[r][q][3], kmm[3]);  FMA2(acc2, wp, E[r][q][3], acc2);
            FMA2(wp, nkm[4], d[r][q][4], kmm[4]);  FMA2(acc,  wp, E[r][q][4], acc);
            FMA2(wp, nkm[5], d[r][q][5], kmm[5]);  FMA2(acc2, wp, E[r][q][5], acc2);
            FMA2(wp, nkm[6], d[r][q][6], kmm[6]);  FMA2(acc,  wp, E[r][q][6], acc);
            FMA2(wp, nkm[7], d[r][q][7], kmm[7]);  FMA2(acc2, wp, E[r][q][7], acc2);
            ADD2(acc, acc, acc2);

            // S += E_j * ( acc*(lj2-d_j) + (alpha + beta d + gamma d^2) * E_j )
            u64 t;  FMA2(t, d[r][q][j], negone, lj2);
            u64 u_; FMA2(u_, ga, d[r][q][j], be);
            u64 py; FMA2(py, d[r][q][j], u_, al);
            u64 v;  MUL2(v, acc, t);
            FMA2(v, py, E[r][q][j], v);
            FMA2(S[r][q], E[r][q][j], v, S[r][q]);
        }
    }

    // ---- outputs: res = sig0 * E0 * S ----
    u64 s0 = sig0d;
#pragma unroll
    for (int r = 0; r < 2; r++) {
        int n = n0 + ty + 4 * r;
        if (n >= N) continue;
#pragma unroll
        for (int q = 0; q < 2; q++) {
            int m = m0 + 2 * (tx + 32 * q);
            if (m >= M) continue;
            u64 e0; MUL2(e0, E[r][q][0], s0);
            u64 res; MUL2(res, S[r][q], e0);
            long idx = (long)n * M + m;
            if (m + 1 < M) {
                *reinterpret_cast<u64*>(&out[idx]) = res;
            } else {
                float lo, hi; unpack2(res, lo, hi);
                out[idx] = lo;
            }
        }
    }
}

extern "C" void kernel_launch(void* const* d_in, const int* in_sizes, int n_in,
                              void* d_out, int out_size)
{
    const float* x1  = (const float*)d_in[0];
    const float* x2  = (const float*)d_in[1];
    const float* L   = (const float*)d_in[2];
    const float* sig = (const float*)d_in[3];
    float* out = (float*)d_out;

    int N = in_sizes[0] / DD;
    int M = in_sizes[1] / DD;

    dim3 block(32, 4);                                     // 128 threads
    dim3 grid((M + 127) / 128, (N + 7) / 8);
    taylor_rbf_kernel<<<grid, block>>>(x1, x2, L, sig, out, N, M);
}

// round 10
// speedup vs baseline: 1.0998x; 1.0218x over previous
#include <cuda_runtime.h>

#define DD 8

typedef unsigned long long u64;

// constant layout: [0..63] w | [64..191] ks (per j: 8x KMm, 8x -Km) | [192..223] pl (per j: lj2,alpha,beta,gamma) | [224] sig0
#define C_W   0
#define C_KS  64
#define C_PL  192
#define C_S0  224
#define C_TOT 232

__constant__ __align__(16) u64 cC[C_TOT];
__device__   __align__(16) u64 gScratch[C_TOT];

// packed f32x2 ops (Blackwell sm_103a)
#define FMA2(d,a,b,c) asm("fma.rn.f32x2 %0, %1, %2, %3;" : "=l"(d) : "l"(a), "l"(b), "l"(c))
#define MUL2(d,a,b)   asm("mul.rn.f32x2 %0, %1, %2;"     : "=l"(d) : "l"(a), "l"(b))
#define ADD2(d,a,b)   asm("add.rn.f32x2 %0, %1, %2;"     : "=l"(d) : "l"(a), "l"(b))

__device__ __forceinline__ u64 pack2(float lo, float hi) {
    u64 r; asm("mov.b64 %0, {%1, %2};" : "=l"(r) : "f"(lo), "f"(hi)); return r;
}
__device__ __forceinline__ void unpack2(u64 v, float& lo, float& hi) {
    asm("mov.b64 {%0, %1}, %2;" : "=f"(lo), "=f"(hi) : "l"(v));
}
__device__ __forceinline__ float ex2a(float x) {
    float r; asm("ex2.approx.f32 %0, %1;" : "=f"(r) : "f"(x)); return r;
}
__device__ __forceinline__ u64 dup(float v) {
    unsigned u = __float_as_uint(v);
    return ((u64)u << 32) | (u64)u;
}

// ---------- setup kernel: derive constants once ----------
__global__ void setup_kernel(const float* __restrict__ L, const float* __restrict__ sig)
{
    int tid = threadIdx.x;            // 0..63
    int c = tid >> 3, j = tid & 7;
    float Ljc = L[j * DD + c];
    float inv2_jc = 1.0f / (Ljc * Ljc);
    float L0c = L[c];
    float inv2_0c = 1.0f / (L0c * L0c);
    float Mcj = inv2_0c + inv2_jc;
    float L0j = L[j];
    float lj2 = L0j * L0j;
    float Kcj = sig[j] / (lj2 * lj2) * Mcj * Mcj;
    gScratch[C_KS + j * 16 + c]     = dup(Kcj / Mcj);
    gScratch[C_KS + j * 16 + 8 + c] = dup(-Kcj);
    float Lak = L[c * DD + j];
    gScratch[C_W + c * DD + j] = dup(-0.5f * 1.44269504088896340736f / (Lak * Lak));
    if (c == j) {
        int l = c;
        float tl = Mcj;                       // M[l][l]
        float c1 = 5.0f * tl + lj2 * tl * tl;
        float c2 = tl * tl;
        float c3 = 2.0f + lj2 * tl;
        float F  = sig[l] / (lj2 * lj2);
        float Kd = Kcj;
        float Md = 1.0f / tl;
        gScratch[C_PL + l * 4 + 0] = dup(lj2);
        gScratch[C_PL + l * 4 + 1] = dup(F * c3 - Kd * Md * lj2);    // alpha
        gScratch[C_PL + l * 4 + 2] = dup(-F * c1 + Kd * (Md + lj2)); // beta
        gScratch[C_PL + l * 4 + 3] = dup(F * c2 - Kd);               // gamma
    }
    if (tid == 0) gScratch[C_S0] = dup(sig[0]);
}

// ---------- main kernel ----------
// out[n,m] = sigma0 * E0 * S_total
//   d_k = (x1[n,k]-x2[m,k])^2 ; E_a = exp2( sum_k d_k * w[a,k] )
//   S_total = sum_j E_j * [ acc_j*(lj2_j - d_j) + (alpha + beta d + gamma d^2)_j * E_j ]
//   acc_j = sum_c (KMm[c,j] - Km[c,j] d_c) E_c
//
// Block tile: 8 n-rows x 128 m-cols. 128 threads (32x4).
// Each thread: 2 rows (ty, ty+4) x 2 m-pairs (tx, tx+32) = 4 packed pairs = 8 outputs.
// Constants come from the constant bank (direct FFMA2 operands, no register residency).

__global__ __launch_bounds__(128, 3) void taylor_rbf_kernel(
    const float* __restrict__ x1, const float* __restrict__ x2,
    float* __restrict__ out, int N, int M)
{
    __shared__ __align__(16) u64 x1d[8 * DD];    // dup(x1[n0+r][k]), r=0..7
    __shared__ __align__(16) u64 nx2[DD * 64];   // (-x2[m0+2p][k], -x2[m0+2p+1][k]), p=0..63

    const int tx = threadIdx.x;          // 0..31
    const int ty = threadIdx.y;          // 0..3
    const int tid = ty * 32 + tx;        // 0..127

    // ---- stage x tiles ----
    const int n0 = blockIdx.y * 8, m0 = blockIdx.x * 128;
#pragma unroll
    for (int i = 0; i < 4; i++) {        // nx2: 512 entries, 4 per thread
        int idx = tid + 128 * i;
        int k = idx >> 6, p = idx & 63;
        int mm = m0 + 2 * p;
        float a = (mm     < M) ? x2[mm * DD + k]       : 0.0f;
        float b = (mm + 1 < M) ? x2[(mm + 1) * DD + k] : 0.0f;
        nx2[k * 64 + p] = pack2(-a, -b);
    }
    if (tid < 64) {                      // x1d: 64 entries
        int r = tid >> 3, k = tid & 7;
        int nn = n0 + r;
        x1d[r * DD + k] = dup((nn < N) ? x1[nn * DD + k] : 0.0f);
    }
    __syncthreads();

    const u64 negone = dup(-1.0f);

    // ---- d for 4 pairs: rows {ty, ty+4}, pair-cols {tx, tx+32} ----
    u64 d[2][2][DD], E[2][2][DD];
#pragma unroll
    for (int k = 0; k < DD; k++) {
        u64 xv0 = nx2[k * 64 + tx];
        u64 xv1 = nx2[k * 64 + tx + 32];
#pragma unroll
        for (int r = 0; r < 2; r++) {
            u64 xr = x1d[(ty + 4 * r) * DD + k];
            u64 f0; ADD2(f0, xr, xv0);  MUL2(d[r][0][k], f0, f0);
            u64 f1; ADD2(f1, xr, xv1);  MUL2(d[r][1][k], f1, f1);
        }
    }

    // ---- E_a = exp2( d . w_a ) for 4 pairs (weights from const bank) ----
#pragma unroll
    for (int a = 0; a < DD; a++) {
        const u64* wr = &cC[C_W + a * DD];
#pragma unroll
        for (int r = 0; r < 2; r++)
#pragma unroll
        for (int q = 0; q < 2; q++) {
            u64 s;
            MUL2(s, d[r][q][0], wr[0]);
            FMA2(s, d[r][q][1], wr[1], s);
            FMA2(s, d[r][q][2], wr[2], s);
            FMA2(s, d[r][q][3], wr[3], s);
            FMA2(s, d[r][q][4], wr[4], s);
            FMA2(s, d[r][q][5], wr[5], s);
            FMA2(s, d[r][q][6], wr[6], s);
            FMA2(s, d[r][q][7], wr[7], s);
            float lo, hi;
            unpack2(s, lo, hi);
            E[r][q][a] = pack2(ex2a(lo), ex2a(hi));
        }
    }

    // ---- merged S + corr loop over j; 4 pairs share each constant read ----
    u64 S[2][2];
    S[0][0] = S[0][1] = S[1][0] = S[1][1] = dup(0.0f);
#pragma unroll
    for (int j = 0; j < DD; j++) {
        const u64* kmm = &cC[C_KS + j * 16];       // 8x KMm
        const u64* nkm = &cC[C_KS + j * 16 + 8];   // 8x -Km
        const u64* pl  = &cC[C_PL + j * 4];        // lj2, alpha, beta, gamma
#pragma unroll
        for (int r = 0; r < 2; r++)
#pragma unroll
        for (int q = 0; q < 2; q++) {
            u64 acc, acc2, wp;
            FMA2(wp, nkm[0], d[r][q][0], kmm[0]);  MUL2(acc,  wp, E[r][q][0]);
            FMA2(wp, nkm[1], d[r][q][1], kmm[1]);  MUL2(acc2, wp, E[r][q][1]);
            FMA2(wp, nkm[2], d[r][q][2], kmm[2]);  FMA2(acc,  wp, E[r][q][2], acc);
            FMA2(wp, nkm[3], d[r][q][3], kmm[3]);  FMA2(acc2, wp, E[r][q][3], acc2);
            FMA2(wp, nkm[4], d[r][q][4], kmm[4]);  FMA2(acc,  wp, E[r][q][4], acc);
            FMA2(wp, nkm[5], d[r][q][5], kmm[5]);  FMA2(acc2, wp, E[r][q][5], acc2);
            FMA2(wp, nkm[6], d[r][q][6], kmm[6]);  FMA2(acc,  wp, E[r][q][6], acc);
            FMA2(wp, nkm[7], d[r][q][7], kmm[7]);  FMA2(acc2, wp, E[r][q][7], acc2);
            ADD2(acc, acc, acc2);

            // S += E_j * ( acc*(lj2-d_j) + (alpha + beta d + gamma d^2) * E_j )
            u64 t;  FMA2(t, d[r][q][j], negone, pl[0]);
            u64 u_; FMA2(u_, pl[3], d[r][q][j], pl[2]);
            u64 py; FMA2(py, d[r][q][j], u_, pl[1]);
            u64 v;  MUL2(v, acc, t);
            FMA2(v, py, E[r][q][j], v);
            FMA2(S[r][q], E[r][q][j], v, S[r][q]);
        }
    }

    // ---- outputs: res = sig0 * E0 * S ----
#pragma unroll
    for (int r = 0; r < 2; r++) {
        int n = n0 + ty + 4 * r;
        if (n >= N) continue;
#pragma unroll
        for (int q = 0; q < 2; q++) {
            int m = m0 + 2 * (tx + 32 * q);
            if (m >= M) continue;
            u64 e0; MUL2(e0, E[r][q][0], cC[C_S0]);
            u64 res; MUL2(res, S[r][q], e0);
            long idx = (long)n * M + m;
            if (m + 1 < M) {
                *reinterpret_cast<u64*>(&out[idx]) = res;
            } else {
                float lo, hi; unpack2(res, lo, hi);
                out[idx] = lo;
            }
        }
    }
}

extern "C" void kernel_launch(void* const* d_in, const int* in_sizes, int n_in,
                              void* d_out, int out_size)
{
    const float* x1  = (const float*)d_in[0];
    const float* x2  = (const float*)d_in[1];
    const float* L   = (const float*)d_in[2];
    const float* sig = (const float*)d_in[3];
    float* out = (float*)d_out;

    int N = in_sizes[0] / DD;
    int M = in_sizes[1] / DD;

    setup_kernel<<<1, 64>>>(L, sig);

    void* scratch_addr = nullptr;
    cudaGetSymbolAddress(&scratch_addr, gScratch);
    cudaMemcpyToSymbolAsync(cC, scratch_addr, C_TOT * sizeof(u64), 0,
                            cudaMemcpyDeviceToDevice, 0);

    dim3 block(32, 4);                                     // 128 threads
    dim3 grid((M + 127) / 128, (N + 7) / 8);
    taylor_rbf_kernel<<<grid, block>>>(x1, x2, out, N, M);
}

// round 11
// speedup vs baseline: 1.1770x; 1.0701x over previous
#include <cuda_runtime.h>

#define DD 8

typedef unsigned long long u64;

// constant layout: [0..63] w | [64..191] ks (per j: 8x KMm, 8x -Km) | [192..223] pl (per j: lj2,alpha,beta,gamma) | [224] sig0
#define C_W   0
#define C_KS  64
#define C_PL  192
#define C_S0  224
#define C_TOT 232

__constant__ __align__(16) u64 cC[C_TOT];

// packed f32x2 ops (Blackwell sm_103a)
#define FMA2(d,a,b,c) asm("fma.rn.f32x2 %0, %1, %2, %3;" : "=l"(d) : "l"(a), "l"(b), "l"(c))
#define MUL2(d,a,b)   asm("mul.rn.f32x2 %0, %1, %2;"     : "=l"(d) : "l"(a), "l"(b))
#define ADD2(d,a,b)   asm("add.rn.f32x2 %0, %1, %2;"     : "=l"(d) : "l"(a), "l"(b))

__device__ __forceinline__ u64 pack2(float lo, float hi) {
    u64 r; asm("mov.b64 %0, {%1, %2};" : "=l"(r) : "f"(lo), "f"(hi)); return r;
}
__device__ __forceinline__ void unpack2(u64 v, float& lo, float& hi) {
    asm("mov.b64 {%0, %1}, %2;" : "=f"(lo), "=f"(hi) : "l"(v));
}
__device__ __forceinline__ float ex2a(float x) {
    float r; asm("ex2.approx.f32 %0, %1;" : "=f"(r) : "f"(x)); return r;
}
__device__ __forceinline__ u64 dup(float v) {
    unsigned u = __float_as_uint(v);
    return ((u64)u << 32) | (u64)u;
}

// ---------- setup kernel: derive constants, write DIRECTLY into cC's backing store ----------
__global__ void setup_kernel(const float* __restrict__ L, const float* __restrict__ sig,
                             u64* __restrict__ cc)
{
    int tid = threadIdx.x;            // 0..63
    int c = tid >> 3, j = tid & 7;
    float Ljc = L[j * DD + c];
    float inv2_jc = 1.0f / (Ljc * Ljc);
    float L0c = L[c];
    float inv2_0c = 1.0f / (L0c * L0c);
    float Mcj = inv2_0c + inv2_jc;
    float L0j = L[j];
    float lj2 = L0j * L0j;
    float Kcj = sig[j] / (lj2 * lj2) * Mcj * Mcj;
    cc[C_KS + j * 16 + c]     = dup(Kcj / Mcj);
    cc[C_KS + j * 16 + 8 + c] = dup(-Kcj);
    float Lak = L[c * DD + j];
    cc[C_W + c * DD + j] = dup(-0.5f * 1.44269504088896340736f / (Lak * Lak));
    if (c == j) {
        int l = c;
        float tl = Mcj;                       // M[l][l]
        float c1 = 5.0f * tl + lj2 * tl * tl;
        float c2 = tl * tl;
        float c3 = 2.0f + lj2 * tl;
        float F  = sig[l] / (lj2 * lj2);
        float Kd = Kcj;
        float Md = 1.0f / tl;
        cc[C_PL + l * 4 + 0] = dup(lj2);
        cc[C_PL + l * 4 + 1] = dup(F * c3 - Kd * Md * lj2);    // alpha
        cc[C_PL + l * 4 + 2] = dup(-F * c1 + Kd * (Md + lj2)); // beta
        cc[C_PL + l * 4 + 3] = dup(F * c2 - Kd);               // gamma
    }
    if (tid == 0) cc[C_S0] = dup(sig[0]);
}

// ---------- main kernel ----------
// out[n,m] = sigma0 * E0 * S_total
//   d_k = (x1[n,k]-x2[m,k])^2 ; E_a = exp2( sum_k d_k * w[a,k] )
//   S_total = sum_j E_j * [ acc_j*(lj2_j - d_j) + (alpha + beta d + gamma d^2)_j * E_j ]
//   acc_j = sum_c (KMm[c,j] - Km[c,j] d_c) E_c
//
// Block tile: 8 n-rows x 128 m-cols. 128 threads (32x4).
// Each thread: 2 rows (ty, ty+4) x 2 m-pairs (tx, tx+32) = 4 packed pairs = 8 outputs.
// Constants from the constant bank (direct FFMA2 operands, no register residency).

__global__ __launch_bounds__(128, 3) void taylor_rbf_kernel(
    const float* __restrict__ x1, const float* __restrict__ x2,
    float* __restrict__ out, int N, int M)
{
    __shared__ __align__(16) u64 x1d[8 * DD];    // dup(x1[n0+r][k]), r=0..7
    __shared__ __align__(16) u64 nx2[DD * 64];   // (-x2[m0+2p][k], -x2[m0+2p+1][k]), p=0..63

    const int tx = threadIdx.x;          // 0..31
    const int ty = threadIdx.y;          // 0..3
    const int tid = ty * 32 + tx;        // 0..127

    // ---- stage x tiles ----
    const int n0 = blockIdx.y * 8, m0 = blockIdx.x * 128;
#pragma unroll
    for (int i = 0; i < 4; i++) {        // nx2: 512 entries, 4 per thread
        int idx = tid + 128 * i;
        int k = idx >> 6, p = idx & 63;
        int mm = m0 + 2 * p;
        float a = (mm     < M) ? x2[mm * DD + k]       : 0.0f;
        float b = (mm + 1 < M) ? x2[(mm + 1) * DD + k] : 0.0f;
        nx2[k * 64 + p] = pack2(-a, -b);
    }
    if (tid < 64) {                      // x1d: 64 entries
        int r = tid >> 3, k = tid & 7;
        int nn = n0 + r;
        x1d[r * DD + k] = dup((nn < N) ? x1[nn * DD + k] : 0.0f);
    }
    __syncthreads();

    const u64 negone = dup(-1.0f);

    // ---- d for 4 pairs: rows {ty, ty+4}, pair-cols {tx, tx+32} ----
    u64 d[2][2][DD], E[2][2][DD];
#pragma unroll
    for (int k = 0; k < DD; k++) {
        u64 xv0 = nx2[k * 64 + tx];
        u64 xv1 = nx2[k * 64 + tx + 32];
#pragma unroll
        for (int r = 0; r < 2; r++) {
            u64 xr = x1d[(ty + 4 * r) * DD + k];
            u64 f0; ADD2(f0, xr, xv0);  MUL2(d[r][0][k], f0, f0);
            u64 f1; ADD2(f1, xr, xv1);  MUL2(d[r][1][k], f1, f1);
        }
    }

    // ---- E_a = exp2( d . w_a ) for 4 pairs (weights from const bank) ----
#pragma unroll
    for (int a = 0; a < DD; a++) {
        const u64* wr = &cC[C_W + a * DD];
#pragma unroll
        for (int r = 0; r < 2; r++)
#pragma unroll
        for (int q = 0; q < 2; q++) {
            u64 s;
            MUL2(s, d[r][q][0], wr[0]);
            FMA2(s, d[r][q][1], wr[1], s);
            FMA2(s, d[r][q][2], wr[2], s);
            FMA2(s, d[r][q][3], wr[3], s);
            FMA2(s, d[r][q][4], wr[4], s);
            FMA2(s, d[r][q][5], wr[5], s);
            FMA2(s, d[r][q][6], wr[6], s);
            FMA2(s, d[r][q][7], wr[7], s);
            float lo, hi;
            unpack2(s, lo, hi);
            E[r][q][a] = pack2(ex2a(lo), ex2a(hi));
        }
    }

    // ---- merged S + corr loop over j; 4 pairs share each constant read ----
    u64 S[2][2];
    S[0][0] = S[0][1] = S[1][0] = S[1][1] = dup(0.0f);
#pragma unroll
    for (int j = 0; j < DD; j++) {
        const u64* kmm = &cC[C_KS + j * 16];       // 8x KMm
        const u64* nkm = &cC[C_KS + j * 16 + 8];   // 8x -Km
        const u64* pl  = &cC[C_PL + j * 4];        // lj2, alpha, beta, gamma
#pragma unroll
        for (int r = 0; r < 2; r++)
#pragma unroll
        for (int q = 0; q < 2; q++) {
            u64 acc, acc2, wp;
            FMA2(wp, nkm[0], d[r][q][0], kmm[0]);  MUL2(acc,  wp, E[r][q][0]);
            FMA2(wp, nkm[1], d[r][q][1], kmm[1]);  MUL2(acc2, wp, E[r][q][1]);
            FMA2(wp, nkm[2], d[r][q][2], kmm[2]);  FMA2(acc,  wp, E[r][q][2], acc);
            FMA2(wp, nkm[3], d[r][q][3], kmm[3]);  FMA2(acc2, wp, E[r][q][3], acc2);
            FMA2(wp, nkm[4], d[r][q][4], kmm[4]);  FMA2(acc,  wp, E[r][q][4], acc);
            FMA2(wp, nkm[5], d[r][q][5], kmm[5]);  FMA2(acc2, wp, E[r][q][5], acc2);
            FMA2(wp, nkm[6], d[r][q][6], kmm[6]);  FMA2(acc,  wp, E[r][q][6], acc);
            FMA2(wp, nkm[7], d[r][q][7], kmm[7]);  FMA2(acc2, wp, E[r][q][7], acc2);
            ADD2(acc, acc, acc2);

            // S += E_j * ( acc*(lj2-d_j) + (alpha + beta d + gamma d^2) * E_j )
            u64 t;  FMA2(t, d[r][q][j], negone, pl[0]);
            u64 u_; FMA2(u_, pl[3], d[r][q][j], pl[2]);
            u64 py; FMA2(py, d[r][q][j], u_, pl[1]);
            u64 v;  MUL2(v, acc, t);
            FMA2(v, py, E[r][q][j], v);
            FMA2(S[r][q], E[r][q][j], v, S[r][q]);
        }
    }

    // ---- outputs: res = sig0 * E0 * S ----
#pragma unroll
    for (int r = 0; r < 2; r++) {
        int n = n0 + ty + 4 * r;
        if (n >= N) continue;
#pragma unroll
        for (int q = 0; q < 2; q++) {
            int m = m0 + 2 * (tx + 32 * q);
            if (m >= M) continue;
            u64 e0; MUL2(e0, E[r][q][0], cC[C_S0]);
            u64 res; MUL2(res, S[r][q], e0);
            long idx = (long)n * M + m;
            if (m + 1 < M) {
                *reinterpret_cast<u64*>(&out[idx]) = res;
            } else {
                float lo, hi; unpack2(res, lo, hi);
                out[idx] = lo;
            }
        }
    }
}

extern "C" void kernel_launch(void* const* d_in, const int* in_sizes, int n_in,
                              void* d_out, int out_size)
{
    const float* x1  = (const float*)d_in[0];
    const float* x2  = (const float*)d_in[1];
    const float* L   = (const float*)d_in[2];
    const float* sig = (const float*)d_in[3];
    float* out = (float*)d_out;

    int N = in_sizes[0] / DD;
    int M = in_sizes[1] / DD;

    // Write constants straight into cC's backing memory from the setup kernel
    // (no memcpy node; per-launch cache invalidation makes them visible to LDC).
    void* cc_addr = nullptr;
    cudaGetSymbolAddress(&cc_addr, cC);
    setup_kernel<<<1, 64>>>(L, sig, (u64*)cc_addr);

    dim3 block(32, 4);                                     // 128 threads
    dim3 grid((M + 127) / 128, (N + 7) / 8);
    taylor_rbf_kernel<<<grid, block>>>(x1, x2, out, N, M);
}

// round 12
// speedup vs baseline: 1.3378x; 1.1366x over previous
#include <cuda_runtime.h>

#define DD 8

typedef unsigned long long u64;

// constant layout: [0..63] w | [64..191] ks (per j: 8x KMm, 8x -Km) | [192..223] pl (per j: lj2,alpha,beta,gamma) | [224] sig0
#define C_W   0
#define C_KS  64
#define C_PL  192
#define C_S0  224
#define C_TOT 232

__constant__ __align__(16) u64 cC[C_TOT];

// packed f32x2 ops (Blackwell sm_103a)
#define FMA2(d,a,b,c) asm("fma.rn.f32x2 %0, %1, %2, %3;" : "=l"(d) : "l"(a), "l"(b), "l"(c))
#define MUL2(d,a,b)   asm("mul.rn.f32x2 %0, %1, %2;"     : "=l"(d) : "l"(a), "l"(b))
#define ADD2(d,a,b)   asm("add.rn.f32x2 %0, %1, %2;"     : "=l"(d) : "l"(a), "l"(b))

__device__ __forceinline__ u64 pack2(float lo, float hi) {
    u64 r; asm("mov.b64 %0, {%1, %2};" : "=l"(r) : "f"(lo), "f"(hi)); return r;
}
__device__ __forceinline__ void unpack2(u64 v, float& lo, float& hi) {
    asm("mov.b64 {%0, %1}, %2;" : "=f"(lo), "=f"(hi) : "l"(v));
}
__device__ __forceinline__ float ex2a(float x) {
    float r; asm("ex2.approx.f32 %0, %1;" : "=f"(r) : "f"(x)); return r;
}
__device__ __forceinline__ u64 dup(float v) {
    unsigned u = __float_as_uint(v);
    return ((u64)u << 32) | (u64)u;
}

// ---------- setup kernel: derive constants, write DIRECTLY into cC's backing store ----------
__global__ void setup_kernel(const float* __restrict__ L, const float* __restrict__ sig,
                             u64* __restrict__ cc)
{
    // Let the dependent (main) kernel start launching immediately; its
    // griddepcontrol.wait still blocks until this kernel fully completes.
    asm volatile("griddepcontrol.launch_dependents;");

    int tid = threadIdx.x;            // 0..63
    int c = tid >> 3, j = tid & 7;
    float Ljc = L[j * DD + c];
    float inv2_jc = 1.0f / (Ljc * Ljc);
    float L0c = L[c];
    float inv2_0c = 1.0f / (L0c * L0c);
    float Mcj = inv2_0c + inv2_jc;
    float L0j = L[j];
    float lj2 = L0j * L0j;
    float Kcj = sig[j] / (lj2 * lj2) * Mcj * Mcj;
    cc[C_KS + j * 16 + c]     = dup(Kcj / Mcj);
    cc[C_KS + j * 16 + 8 + c] = dup(-Kcj);
    float Lak = L[c * DD + j];
    cc[C_W + c * DD + j] = dup(-0.5f * 1.44269504088896340736f / (Lak * Lak));
    if (c == j) {
        int l = c;
        float tl = Mcj;                       // M[l][l]
        float c1 = 5.0f * tl + lj2 * tl * tl;
        float c2 = tl * tl;
        float c3 = 2.0f + lj2 * tl;
        float F  = sig[l] / (lj2 * lj2);
        float Kd = Kcj;
        float Md = 1.0f / tl;
        cc[C_PL + l * 4 + 0] = dup(lj2);
        cc[C_PL + l * 4 + 1] = dup(F * c3 - Kd * Md * lj2);    // alpha
        cc[C_PL + l * 4 + 2] = dup(-F * c1 + Kd * (Md + lj2)); // beta
        cc[C_PL + l * 4 + 3] = dup(F * c2 - Kd);               // gamma
    }
    if (tid == 0) cc[C_S0] = dup(sig[0]);
}

// ---------- main kernel ----------
// out[n,m] = sigma0 * E0 * S_total
//   d_k = (x1[n,k]-x2[m,k])^2 ; E_a = exp2( sum_k d_k * w[a,k] )
//   S_total = sum_j E_j * [ acc_j*(lj2_j - d_j) + (alpha + beta d + gamma d^2)_j * E_j ]
//   acc_j = sum_c (KMm[c,j] - Km[c,j] d_c) E_c
//
// Block tile: 8 n-rows x 128 m-cols. 128 threads (32x4).
// Each thread: 2 rows (ty, ty+4) x 2 m-pairs (tx, tx+32) = 4 packed pairs = 8 outputs.
// Constants from the constant bank. PDL: staging + d computation overlap the
// setup kernel; griddepcontrol.wait precedes the first cC access.

__global__ __launch_bounds__(128, 3) void taylor_rbf_kernel(
    const float* __restrict__ x1, const float* __restrict__ x2,
    float* __restrict__ out, int N, int M)
{
    __shared__ __align__(16) u64 x1d[8 * DD];    // dup(x1[n0+r][k]), r=0..7
    __shared__ __align__(16) u64 nx2[DD * 64];   // (-x2[m0+2p][k], -x2[m0+2p+1][k]), p=0..63

    const int tx = threadIdx.x;          // 0..31
    const int ty = threadIdx.y;          // 0..3
    const int tid = ty * 32 + tx;        // 0..127

    // ---- stage x tiles (no cC access here) ----
    const int n0 = blockIdx.y * 8, m0 = blockIdx.x * 128;
#pragma unroll
    for (int i = 0; i < 4; i++) {        // nx2: 512 entries, 4 per thread
        int idx = tid + 128 * i;
        int k = idx >> 6, p = idx & 63;
        int mm = m0 + 2 * p;
        float a = (mm     < M) ? x2[mm * DD + k]       : 0.0f;
        float b = (mm + 1 < M) ? x2[(mm + 1) * DD + k] : 0.0f;
        nx2[k * 64 + p] = pack2(-a, -b);
    }
    if (tid < 64) {                      // x1d: 64 entries
        int r = tid >> 3, k = tid & 7;
        int nn = n0 + r;
        x1d[r * DD + k] = dup((nn < N) ? x1[nn * DD + k] : 0.0f);
    }
    __syncthreads();

    const u64 negone = dup(-1.0f);

    // ---- d for 4 pairs: rows {ty, ty+4}, pair-cols {tx, tx+32} (no cC access) ----
    u64 d[2][2][DD], E[2][2][DD];
#pragma unroll
    for (int k = 0; k < DD; k++) {
        u64 xv0 = nx2[k * 64 + tx];
        u64 xv1 = nx2[k * 64 + tx + 32];
#pragma unroll
        for (int r = 0; r < 2; r++) {
            u64 xr = x1d[(ty + 4 * r) * DD + k];
            u64 f0; ADD2(f0, xr, xv0);  MUL2(d[r][0][k], f0, f0);
            u64 f1; ADD2(f1, xr, xv1);  MUL2(d[r][1][k], f1, f1);
        }
    }

    // ---- PDL sync: setup kernel's constant writes must be visible below ----
    asm volatile("griddepcontrol.wait;" ::: "memory");

    // ---- E_a = exp2( d . w_a ) for 4 pairs (weights from const bank) ----
#pragma unroll
    for (int a = 0; a < DD; a++) {
        const u64* wr = &cC[C_W + a * DD];
#pragma unroll
        for (int r = 0; r < 2; r++)
#pragma unroll
        for (int q = 0; q < 2; q++) {
            u64 s;
            MUL2(s, d[r][q][0], wr[0]);
            FMA2(s, d[r][q][1], wr[1], s);
            FMA2(s, d[r][q][2], wr[2], s);
            FMA2(s, d[r][q][3], wr[3], s);
            FMA2(s, d[r][q][4], wr[4], s);
            FMA2(s, d[r][q][5], wr[5], s);
            FMA2(s, d[r][q][6], wr[6], s);
            FMA2(s, d[r][q][7], wr[7], s);
            float lo, hi;
            unpack2(s, lo, hi);
            E[r][q][a] = pack2(ex2a(lo), ex2a(hi));
        }
    }

    // ---- merged S + corr loop over j; 4 pairs share each constant read ----
    u64 S[2][2];
    S[0][0] = S[0][1] = S[1][0] = S[1][1] = dup(0.0f);
#pragma unroll
    for (int j = 0; j < DD; j++) {
        const u64* kmm = &cC[C_KS + j * 16];       // 8x KMm
        const u64* nkm = &cC[C_KS + j * 16 + 8];   // 8x -Km
        const u64* pl  = &cC[C_PL + j * 4];        // lj2, alpha, beta, gamma
#pragma unroll
        for (int r = 0; r < 2; r++)
#pragma unroll
        for (int q = 0; q < 2; q++) {
            u64 acc, acc2, wp;
            FMA2(wp, nkm[0], d[r][q][0], kmm[0]);  MUL2(acc,  wp, E[r][q][0]);
            FMA2(wp, nkm[1], d[r][q][1], kmm[1]);  MUL2(acc2, wp, E[r][q][1]);
            FMA2(wp, nkm[2], d[r][q][2], kmm[2]);  FMA2(acc,  wp, E[r][q][2], acc);
            FMA2(wp, nkm[3], d[r][q][3], kmm[3]);  FMA2(acc2, wp, E[r][q][3], acc2);
            FMA2(wp, nkm[4], d[r][q][4], kmm[4]);  FMA2(acc,  wp, E[r][q][4], acc);
            FMA2(wp, nkm[5], d[r][q][5], kmm[5]);  FMA2(acc2, wp, E[r][q][5], acc2);
            FMA2(wp, nkm[6], d[r][q][6], kmm[6]);  FMA2(acc,  wp, E[r][q][6], acc);
            FMA2(wp, nkm[7], d[r][q][7], kmm[7]);  FMA2(acc2, wp, E[r][q][7], acc2);
            ADD2(acc, acc, acc2);

            // S += E_j * ( acc*(lj2-d_j) + (alpha + beta d + gamma d^2) * E_j )
            u64 t;  FMA2(t, d[r][q][j], negone, pl[0]);
            u64 u_; FMA2(u_, pl[3], d[r][q][j], pl[2]);
            u64 py; FMA2(py, d[r][q][j], u_, pl[1]);
            u64 v;  MUL2(v, acc, t);
            FMA2(v, py, E[r][q][j], v);
            FMA2(S[r][q], E[r][q][j], v, S[r][q]);
        }
    }

    // ---- outputs: res = sig0 * E0 * S ----
#pragma unroll
    for (int r = 0; r < 2; r++) {
        int n = n0 + ty + 4 * r;
        if (n >= N) continue;
#pragma unroll
        for (int q = 0; q < 2; q++) {
            int m = m0 + 2 * (tx + 32 * q);
            if (m >= M) continue;
            u64 e0; MUL2(e0, E[r][q][0], cC[C_S0]);
            u64 res; MUL2(res, S[r][q], e0);
            long idx = (long)n * M + m;
            if (m + 1 < M) {
                *reinterpret_cast<u64*>(&out[idx]) = res;
            } else {
                float lo, hi; unpack2(res, lo, hi);
                out[idx] = lo;
            }
        }
    }
}

extern "C" void kernel_launch(void* const* d_in, const int* in_sizes, int n_in,
                              void* d_out, int out_size)
{
    const float* x1  = (const float*)d_in[0];
    const float* x2  = (const float*)d_in[1];
    const float* L   = (const float*)d_in[2];
    const float* sig = (const float*)d_in[3];
    float* out = (float*)d_out;

    int N = in_sizes[0] / DD;
    int M = in_sizes[1] / DD;

    void* cc_addr = nullptr;
    cudaGetSymbolAddress(&cc_addr, cC);
    setup_kernel<<<1, 64>>>(L, sig, (u64*)cc_addr);

    // Main kernel with Programmatic Dependent Launch: overlaps its launch +
    // constant-free preamble with the setup kernel.
    dim3 block(32, 4);                                     // 128 threads
    dim3 grid((M + 127) / 128, (N + 7) / 8);

    cudaLaunchConfig_t cfg = {};
    cfg.gridDim = grid;
    cfg.blockDim = block;
    cfg.dynamicSmemBytes = 0;
    cfg.stream = 0;
    cudaLaunchAttribute attrs[1];
    attrs[0].id = cudaLaunchAttributeProgrammaticStreamSerialization;
    attrs[0].val.programmaticStreamSerializationAllowed = 1;
    cfg.attrs = attrs;
    cfg.numAttrs = 1;

    cudaLaunchKernelEx(&cfg, taylor_rbf_kernel, x1, x2, out, N, M);
}